// round 4
// baseline (speedup 1.0000x reference)
#include <cuda_runtime.h>
#include <math.h>

#define NPTS    32768
#define WIDTH   192
#define COND    64
#define KNN     12
#define NLAYERS 4
#define MIXDIM  390
#define MIXPAD  392
#define TPL     32      // points per block (proj)
#define TPL2    16      // points per tile (layer)
#define NTILES  (NPTS / TPL2)   // 2048
#define LGRID   512     // layer grid (tiles strided)

// ---- quantile grid for kNN ----
#define G       16
#define NCELLS  (G*G*G)          // 4096

typedef unsigned long long ull;

// ---- scratch (static device allocations; no cudaMalloc allowed) ----
__device__ float  g_h0[NPTS * WIDTH];
__device__ float  g_h1[NPTS * WIDTH];
__device__ int    g_knn[NPTS * KNN];
__device__ float  g_rel[NPTS * 6];
__device__ float  g_zwpb[WIDTH];
__device__ float  g_gamma[NLAYERS * WIDTH];
__device__ float  g_beta[NLAYERS * WIDTH];

__device__ float  g_bx[G + 1];        // quantile boundaries in x-space
__device__ int    g_cnt[NCELLS];
__device__ int2   g_cell2[NCELLS];    // (start, end)
__device__ float4 g_pts[NPTS];        // sorted (x,y,z, orig-idx-as-bits)

// ---- packed f32x2 helpers (FFMA2) ----
__device__ __forceinline__ ull pk2(float a, float b) {
    ull r; asm("mov.b64 %0,{%1,%2};" : "=l"(r) : "f"(a), "f"(b)); return r;
}
__device__ __forceinline__ ull fma2(ull a, ull b, ull c) {
    ull d; asm("fma.rn.f32x2 %0,%1,%2,%3;" : "=l"(d) : "l"(a), "l"(b), "l"(c)); return d;
}
__device__ __forceinline__ void upk2(ull v, float& a, float& b) {
    asm("mov.b64 {%0,%1},%2;" : "=f"(a), "=f"(b) : "l"(v));
}

__device__ __forceinline__ int cell_of(float v, const float* bx) {
    int lo = 0;
    if (v >= bx[8])      lo = 8;
    if (v >= bx[lo + 4]) lo += 4;
    if (v >= bx[lo + 2]) lo += 2;
    if (v >= bx[lo + 1]) lo += 1;
    return lo;           // bx[lo] <= v < bx[lo+1]
}

// ============================================================
// Setup: z-dependent constants + quantile boundaries
// ============================================================
__global__ void setup_kernel(const float* __restrict__ z,
                             const float* __restrict__ Wp, const float* __restrict__ bp,
                             const float* __restrict__ Wg, const float* __restrict__ bg,
                             const float* __restrict__ Wb, const float* __restrict__ bb) {
    int c = threadIdx.x;
    if (c <= G) {
        g_bx[c] = (c == 0) ? -1e9f : ((c == G) ? 1e9f
                  : normcdfinvf((float)c / (float)G));
    }
    if (c >= WIDTH) return;
    float s = bp[c];
    for (int k = 0; k < COND; k++)
        s = fmaf(z[k], Wp[(51 + k) * WIDTH + c], s);
    g_zwpb[c] = s;
    for (int li = 0; li < NLAYERS; li++) {
        const float* wg = Wg + li * COND * WIDTH;
        const float* wb = Wb + li * COND * WIDTH;
        float g = bg[li * WIDTH + c];
        float b = bb[li * WIDTH + c];
        for (int k = 0; k < COND; k++) {
            float zk = z[k];
            g = fmaf(zk, wg[k * WIDTH + c], g);
            b = fmaf(zk, wb[k * WIDTH + c], b);
        }
        g_gamma[li * WIDTH + c] = g;
        g_beta[li * WIDTH + c]  = b;
    }
}

// ============================================================
// Grid build: histogram, then fused scan+scatter (1 block)
// ============================================================
__global__ void hist_kernel(const float* __restrict__ x, int n) {
    int i = blockIdx.x * blockDim.x + threadIdx.x;
    if (i >= n) return;
    const float* bx = g_bx;
    int cx = cell_of(x[i * 3 + 0], bx);
    int cy = cell_of(x[i * 3 + 1], bx);
    int cz = cell_of(x[i * 3 + 2], bx);
    atomicAdd(&g_cnt[(cz * G + cy) * G + cx], 1);
}

__global__ __launch_bounds__(1024) void scan_scatter_kernel(const float* __restrict__ x, int n) {
    __shared__ int sh[1024];
    __shared__ int scur[NCELLS];     // 16 KB smem cursors
    __shared__ float bxs[G + 1];
    int t = threadIdx.x;
    if (t <= G) bxs[t] = g_bx[t];

    int4 v = *reinterpret_cast<const int4*>(&g_cnt[t * 4]);
    int s = v.x + v.y + v.z + v.w;
    sh[t] = s;
    __syncthreads();
    for (int off = 1; off < 1024; off <<= 1) {
        int u = (t >= off) ? sh[t - off] : 0;
        __syncthreads();
        sh[t] += u;
        __syncthreads();
    }
    int ex = sh[t] - s;
    int st0 = ex, st1 = st0 + v.x, st2 = st1 + v.y, st3 = st2 + v.z;
    scur[t * 4 + 0] = st0;  g_cell2[t * 4 + 0] = make_int2(st0, st1);
    scur[t * 4 + 1] = st1;  g_cell2[t * 4 + 1] = make_int2(st1, st2);
    scur[t * 4 + 2] = st2;  g_cell2[t * 4 + 2] = make_int2(st2, st3);
    scur[t * 4 + 3] = st3;  g_cell2[t * 4 + 3] = make_int2(st3, st3 + v.w);
    __syncthreads();

    for (int i = t; i < n; i += 1024) {
        float px = x[i * 3 + 0], py = x[i * 3 + 1], pz = x[i * 3 + 2];
        int cx = cell_of(px, bxs), cy = cell_of(py, bxs), cz = cell_of(pz, bxs);
        int cell = (cz * G + cy) * G + cx;
        int slot = atomicAdd(&scur[cell], 1);
        g_pts[slot] = make_float4(px, py, pz, __int_as_float(i));
    }
}

// ============================================================
// kNN query: quantile grid, expanding Chebyshev rings, exact
// AABB pruning + exact stop rule. Unsorted top-12 w/ max-slot.
// ============================================================
__global__ __launch_bounds__(256) void knn_query_kernel(int n) {
    __shared__ float bx[G + 1];
    if (threadIdx.x <= G) bx[threadIdx.x] = g_bx[threadIdx.x];
    __syncthreads();

    int s = blockIdx.x * blockDim.x + threadIdx.x;
    if (s >= n) return;
    float4 me = g_pts[s];
    float qx = me.x, qy = me.y, qz = me.z;
    int   qi = __float_as_int(me.w);
    int cx = cell_of(qx, bx), cy = cell_of(qy, bx), cz = cell_of(qz, bx);

    float bd[KNN];
    int   bj[KNN];                    // sorted-array slots
#pragma unroll
    for (int r = 0; r < KNN; r++) { bd[r] = 1e30f; bj[r] = 0; }
    float dmax = 1e30f;
    int   imax = 0;

    for (int r = 0; r < G; r++) {
        int zlo = max(cz - r, 0), zhi = min(cz + r, G - 1);
        for (int ccz = zlo; ccz <= zhi; ccz++) {
            bool zface = (ccz == cz - r) || (ccz == cz + r);
            float az = fmaxf(fmaxf(bx[ccz] - qz, qz - bx[ccz + 1]), 0.0f);
            int ylo = max(cy - r, 0), yhi = min(cy + r, G - 1);
            for (int ccy = ylo; ccy <= yhi; ccy++) {
                bool face = zface || (ccy == cy - r) || (ccy == cy + r);
                float ay = fmaxf(fmaxf(bx[ccy] - qy, qy - bx[ccy + 1]), 0.0f);
                float ayz = fmaf(ay, ay, az * az);
                if (ayz >= dmax) continue;
                int step = face ? 1 : (2 * r);
                for (int dx = -r; dx <= r; dx += step) {
                    int ccx = cx + dx;
                    if (ccx < 0 || ccx >= G) continue;
                    float ax = fmaxf(fmaxf(bx[ccx] - qx, qx - bx[ccx + 1]), 0.0f);
                    float dmin = fmaf(ax, ax, ayz);
                    if (dmin >= dmax) continue;
                    int2 se = g_cell2[(ccz * G + ccy) * G + ccx];
                    for (int j = se.x; j < se.y; j++) {
                        float4 p = g_pts[j];
                        float ddx = p.x - qx, ddy = p.y - qy, ddz = p.z - qz;
                        float d = fmaf(ddx, ddx, fmaf(ddy, ddy, ddz * ddz));
                        if (d < dmax && j != s) {
                            bd[imax] = d;
                            bj[imax] = j;
                            dmax = bd[0]; imax = 0;
#pragma unroll
                            for (int t = 1; t < KNN; t++)
                                if (bd[t] > dmax) { dmax = bd[t]; imax = t; }
                        }
                    }
                }
            }
        }
        // exact stop: min distance from q to complement of searched box
        float f = 1e30f;
        if (cx - r > 0)      f = fminf(f, qx - bx[cx - r]);
        if (cx + r + 1 < G)  f = fminf(f, bx[cx + r + 1] - qx);
        if (cy - r > 0)      f = fminf(f, qy - bx[cy - r]);
        if (cy + r + 1 < G)  f = fminf(f, bx[cy + r + 1] - qy);
        if (cz - r > 0)      f = fminf(f, qz - bx[cz - r]);
        if (cz + r + 1 < G)  f = fminf(f, bx[cz + r + 1] - qz);
        if (f * f >= dmax) break;
    }

    // emit indices + rel_feat (single pass: mean & E[r^2]-m^2 std)
    float sx = 0, sy = 0, sz = 0, sxx = 0, syy = 0, szz = 0;
#pragma unroll
    for (int r = 0; r < KNN; r++) {
        float4 p = g_pts[bj[r]];
        g_knn[qi * KNN + r] = __float_as_int(p.w);
        float rx = p.x - qx, ry = p.y - qy, rz = p.z - qz;
        sx += rx; sy += ry; sz += rz;
        sxx = fmaf(rx, rx, sxx); syy = fmaf(ry, ry, syy); szz = fmaf(rz, rz, szz);
    }
    const float inv = 1.0f / (float)KNN;
    float mx = sx * inv, my = sy * inv, mz = sz * inv;
    g_rel[qi * 6 + 0] = mx;
    g_rel[qi * 6 + 1] = my;
    g_rel[qi * 6 + 2] = mz;
    g_rel[qi * 6 + 3] = sqrtf(fmaxf(sxx * inv - mx * mx, 0.0f));
    g_rel[qi * 6 + 4] = sqrtf(fmaxf(syy * inv - my * my, 0.0f));
    g_rel[qi * 6 + 5] = sqrtf(fmaxf(szz * inv - mz * mz, 0.0f));
}

// ============================================================
// Projection: pe = fourier(x) (51 dims), h0 = silu(pe@Wp[0:51] + zwpb)
// ============================================================
__global__ __launch_bounds__(192) void proj_kernel(const float* __restrict__ x,
                                                   const float* __restrict__ B0,
                                                   const float* __restrict__ B1,
                                                   const float* __restrict__ B2,
                                                   const float* __restrict__ Wp,
                                                   float* __restrict__ hout) {
    __shared__ float pe[TPL][52];
    int c    = threadIdx.x;
    int base = blockIdx.x * TPL;

    if (c < TPL) {
        int p = base + c;
        float x0 = x[p * 3 + 0], x1 = x[p * 3 + 1], x2 = x[p * 3 + 2];
        const float* Bs[3] = { B0, B1, B2 };
#pragma unroll
        for (int b = 0; b < 3; b++) {
            const float* B = Bs[b];
#pragma unroll
            for (int j = 0; j < 8; j++) {
                float v = fmaf(x0, B[j], fmaf(x1, B[8 + j], x2 * B[16 + j]));
                float sn, cs;
                sincosf(v, &sn, &cs);
                pe[c][b * 16 + j]     = sn;
                pe[c][b * 16 + 8 + j] = cs;
            }
        }
        pe[c][48] = x0; pe[c][49] = x1; pe[c][50] = x2;
    }
    __syncthreads();

    float acc[TPL];
    float zb = g_zwpb[c];
#pragma unroll
    for (int p = 0; p < TPL; p++) acc[p] = zb;
    for (int k = 0; k < 51; k++) {
        float w = Wp[k * WIDTH + c];
#pragma unroll
        for (int p = 0; p < TPL; p++)
            acc[p] = fmaf(pe[p][k], w, acc[p]);
    }
#pragma unroll
    for (int p = 0; p < TPL; p++) {
        float v = acc[p];
        hout[(base + p) * WIDTH + c] = v / (1.0f + expf(-v));
    }
}

// ============================================================
// Layer: gather+mean agg, mix=[h|agg|rel], 390x192 GEMM with
// packed f32x2 FMA, silu + FiLM. Grid-strided tiles (weight reuse).
// ============================================================
__global__ __launch_bounds__(192) void layer_kernel(const float* __restrict__ hin,
                                                    float* __restrict__ hout,
                                                    const float* __restrict__ Wl,
                                                    const float* __restrict__ bl,
                                                    const float* __restrict__ gamma,
                                                    const float* __restrict__ beta) {
    __shared__ float mix[TPL2 * MIXPAD];     // 25088 B
    __shared__ int   nidx[TPL2 * KNN];       // 192
    int c = threadIdx.x;
    float bc = bl[c], gc = gamma[c], bt = beta[c];

    for (int tile = blockIdx.x; tile < NTILES; tile += LGRID) {
        int base = tile * TPL2;

        nidx[c] = g_knn[base * KNN + c];     // 192 = 16*12
        __syncthreads();

#pragma unroll
        for (int p = 0; p < TPL2; p++)
            mix[p * MIXPAD + c] = hin[(base + p) * WIDTH + c];
        if (c < 6) {
#pragma unroll
            for (int p = 0; p < TPL2; p++)
                mix[p * MIXPAD + 384 + c] = g_rel[(base + p) * 6 + c];
        }
#pragma unroll 2
        for (int p = 0; p < TPL2; p++) {
            float s = 0.0f;
#pragma unroll
            for (int j = 0; j < KNN; j++)
                s += hin[nidx[p * KNN + j] * WIDTH + c];
            mix[p * MIXPAD + WIDTH + c] = s * (1.0f / (float)KNN);
        }
        __syncthreads();

        ull acc[TPL2];
#pragma unroll
        for (int p = 0; p < TPL2; p++) acc[p] = 0ull;

        for (int k4 = 0; k4 < 97; k4++) {
            int k = k4 * 4;
            float w0 = Wl[(k + 0) * WIDTH + c];
            float w1 = Wl[(k + 1) * WIDTH + c];
            float w2 = Wl[(k + 2) * WIDTH + c];
            float w3 = Wl[(k + 3) * WIDTH + c];
            ull w01 = pk2(w0, w1), w23 = pk2(w2, w3);
#pragma unroll
            for (int p = 0; p < TPL2; p++) {
                ulonglong2 m = *reinterpret_cast<const ulonglong2*>(&mix[p * MIXPAD + k]);
                acc[p] = fma2(m.x, w01, acc[p]);
                acc[p] = fma2(m.y, w23, acc[p]);
            }
        }
        {   // tail k = 388, 389
            ull w01 = pk2(Wl[388 * WIDTH + c], Wl[389 * WIDTH + c]);
#pragma unroll
            for (int p = 0; p < TPL2; p++) {
                ull m = *reinterpret_cast<const ull*>(&mix[p * MIXPAD + 388]);
                acc[p] = fma2(m, w01, acc[p]);
            }
        }

#pragma unroll
        for (int p = 0; p < TPL2; p++) {
            float a, b;
            upk2(acc[p], a, b);
            float v  = a + b + bc;
            float sv = v / (1.0f + expf(-v));
            hout[(base + p) * WIDTH + c] = fmaf(sv, gc, bt);
        }
        __syncthreads();   // protect mix before next tile overwrites
    }
}

// ============================================================
// Output: out = (h @ Wout + bout) * 0.01 ; one warp per point
// ============================================================
__global__ __launch_bounds__(256) void out_kernel(const float* __restrict__ h,
                                                  const float* __restrict__ Wout,
                                                  const float* __restrict__ bout,
                                                  float* __restrict__ out, int n) {
    int gwarp = (blockIdx.x * blockDim.x + threadIdx.x) >> 5;
    int lane  = threadIdx.x & 31;
    if (gwarp >= n) return;
    float o0 = 0, o1 = 0, o2 = 0;
    for (int c = lane; c < WIDTH; c += 32) {
        float hv = h[gwarp * WIDTH + c];
        o0 = fmaf(hv, Wout[c * 3 + 0], o0);
        o1 = fmaf(hv, Wout[c * 3 + 1], o1);
        o2 = fmaf(hv, Wout[c * 3 + 2], o2);
    }
#pragma unroll
    for (int off = 16; off; off >>= 1) {
        o0 += __shfl_down_sync(0xffffffffu, o0, off);
        o1 += __shfl_down_sync(0xffffffffu, o1, off);
        o2 += __shfl_down_sync(0xffffffffu, o2, off);
    }
    if (lane == 0) {
        out[gwarp * 3 + 0] = (o0 + bout[0]) * 0.01f;
        out[gwarp * 3 + 1] = (o1 + bout[1]) * 0.01f;
        out[gwarp * 3 + 2] = (o2 + bout[2]) * 0.01f;
    }
}

// ============================================================
extern "C" void kernel_launch(void* const* d_in, const int* in_sizes, int n_in,
                              void* d_out, int out_size) {
    const float* x    = (const float*)d_in[0];
    const float* z    = (const float*)d_in[1];
    const float* B0   = (const float*)d_in[2];
    const float* B1   = (const float*)d_in[3];
    const float* B2   = (const float*)d_in[4];
    const float* Wp   = (const float*)d_in[5];
    const float* bp   = (const float*)d_in[6];
    const float* Wl   = (const float*)d_in[7];
    const float* bl   = (const float*)d_in[8];
    const float* Wg   = (const float*)d_in[9];
    const float* bg   = (const float*)d_in[10];
    const float* Wb   = (const float*)d_in[11];
    const float* Wbb  = (const float*)d_in[12];
    const float* Wout = (const float*)d_in[13];
    const float* bout = (const float*)d_in[14];
    float* out = (float*)d_out;

    int n = in_sizes[0] / 3;   // 32768

    float *h0, *h1;
    cudaGetSymbolAddress((void**)&h0, g_h0);
    cudaGetSymbolAddress((void**)&h1, g_h1);
    float *gma, *bta;
    cudaGetSymbolAddress((void**)&gma, g_gamma);
    cudaGetSymbolAddress((void**)&bta, g_beta);
    void* cntp;
    cudaGetSymbolAddress(&cntp, g_cnt);

    cudaMemsetAsync(cntp, 0, NCELLS * sizeof(int));
    setup_kernel<<<1, WIDTH>>>(z, Wp, bp, Wg, bg, Wb, Wbb);          // launch 0
    hist_kernel<<<n / 256, 256>>>(x, n);                             // launch 1
    scan_scatter_kernel<<<1, 1024>>>(x, n);                          // launch 2
    knn_query_kernel<<<n / 256, 256>>>(n);                           // launch 3 (profiled)
    proj_kernel<<<n / TPL, WIDTH>>>(x, B0, B1, B2, Wp, h0);          // launch 4

    float* bufs[2] = { h0, h1 };
    for (int li = 0; li < NLAYERS; li++) {
        const float* hin = bufs[li & 1];
        float*       ho  = bufs[(li + 1) & 1];
        layer_kernel<<<LGRID, 192>>>(hin, ho,
            Wl + (size_t)li * MIXDIM * WIDTH, bl + li * WIDTH,
            gma + li * WIDTH, bta + li * WIDTH);
    }
    const float* hfin = bufs[NLAYERS & 1];

    out_kernel<<<(n * 32 + 255) / 256, 256>>>(hfin, Wout, bout, out, n);
}

// round 6
// speedup vs baseline: 1.2192x; 1.2192x over previous
#include <cuda_runtime.h>
#include <math.h>

#define NPTS    32768
#define WIDTH   192
#define COND    64
#define KNN     12
#define NLAYERS 4
#define MIXDIM  390
#define MIXPAD  392
#define TPL     32      // points per block (proj)
#define TPL2    16      // points per block (layer)

// ---- quantile grid for kNN ----
#define G       16
#define NCELLS  (G*G*G)          // 4096

typedef unsigned long long ull;

// ---- scratch (static device allocations; no cudaMalloc allowed) ----
__device__ float  g_h0[NPTS * WIDTH];
__device__ float  g_h1[NPTS * WIDTH];
__device__ int    g_knn[NPTS * KNN];
__device__ float  g_rel[NPTS * 6];
__device__ float  g_zwpb[WIDTH];
__device__ float  g_gamma[NLAYERS * WIDTH];
__device__ float  g_beta[NLAYERS * WIDTH];

__device__ float  g_bx[G + 1];        // quantile boundaries in x-space
__device__ int    g_cnt[NCELLS];
__device__ int    g_cursor[NCELLS];
__device__ int2   g_cell2[NCELLS];    // (start, end)
__device__ float4 g_pts[NPTS];        // sorted (x,y,z, orig-idx-as-bits)

// ---- packed f32x2 helpers (FFMA2) ----
__device__ __forceinline__ ull pk2(float a, float b) {
    ull r; asm("mov.b64 %0,{%1,%2};" : "=l"(r) : "f"(a), "f"(b)); return r;
}
__device__ __forceinline__ ull fma2(ull a, ull b, ull c) {
    ull d; asm("fma.rn.f32x2 %0,%1,%2,%3;" : "=l"(d) : "l"(a), "l"(b), "l"(c)); return d;
}
__device__ __forceinline__ void upk2(ull v, float& a, float& b) {
    asm("mov.b64 {%0,%1},%2;" : "=f"(a), "=f"(b) : "l"(v));
}

__device__ __forceinline__ int cell_of(float v, const float* bx) {
    int lo = 0;
    if (v >= bx[8])      lo = 8;
    if (v >= bx[lo + 4]) lo += 4;
    if (v >= bx[lo + 2]) lo += 2;
    if (v >= bx[lo + 1]) lo += 1;
    return lo;           // bx[lo] <= v < bx[lo+1]
}

// ============================================================
// Setup: z-dependent constants + quantile boundaries
// ============================================================
__global__ void setup_kernel(const float* __restrict__ z,
                             const float* __restrict__ Wp, const float* __restrict__ bp,
                             const float* __restrict__ Wg, const float* __restrict__ bg,
                             const float* __restrict__ Wb, const float* __restrict__ bb) {
    int c = threadIdx.x;
    if (c <= G) {
        g_bx[c] = (c == 0) ? -1e9f : ((c == G) ? 1e9f
                  : normcdfinvf((float)c / (float)G));
    }
    if (c >= WIDTH) return;
    float s = bp[c];
    for (int k = 0; k < COND; k++)
        s = fmaf(z[k], Wp[(51 + k) * WIDTH + c], s);
    g_zwpb[c] = s;
    for (int li = 0; li < NLAYERS; li++) {
        const float* wg = Wg + li * COND * WIDTH;
        const float* wb = Wb + li * COND * WIDTH;
        float g = bg[li * WIDTH + c];
        float b = bb[li * WIDTH + c];
        for (int k = 0; k < COND; k++) {
            float zk = z[k];
            g = fmaf(zk, wg[k * WIDTH + c], g);
            b = fmaf(zk, wb[k * WIDTH + c], b);
        }
        g_gamma[li * WIDTH + c] = g;
        g_beta[li * WIDTH + c]  = b;
    }
}

// ============================================================
// Grid build: histogram -> single-block scan -> scatter
// ============================================================
__global__ void hist_kernel(const float* __restrict__ x, int n) {
    int i = blockIdx.x * blockDim.x + threadIdx.x;
    if (i >= n) return;
    const float* bx = g_bx;
    int cx = cell_of(x[i * 3 + 0], bx);
    int cy = cell_of(x[i * 3 + 1], bx);
    int cz = cell_of(x[i * 3 + 2], bx);
    atomicAdd(&g_cnt[(cz * G + cy) * G + cx], 1);
}

__global__ void scan_kernel() {   // 1024 threads, 4 cells each
    __shared__ int sh[1024];
    int t = threadIdx.x;
    int4 v = *reinterpret_cast<const int4*>(&g_cnt[t * 4]);
    int s = v.x + v.y + v.z + v.w;
    sh[t] = s;
    __syncthreads();
    for (int off = 1; off < 1024; off <<= 1) {
        int u = (t >= off) ? sh[t - off] : 0;
        __syncthreads();
        sh[t] += u;
        __syncthreads();
    }
    int ex = sh[t] - s;
    int st0 = ex, st1 = st0 + v.x, st2 = st1 + v.y, st3 = st2 + v.z;
    g_cursor[t * 4 + 0] = st0;  g_cell2[t * 4 + 0] = make_int2(st0, st1);
    g_cursor[t * 4 + 1] = st1;  g_cell2[t * 4 + 1] = make_int2(st1, st2);
    g_cursor[t * 4 + 2] = st2;  g_cell2[t * 4 + 2] = make_int2(st2, st3);
    g_cursor[t * 4 + 3] = st3;  g_cell2[t * 4 + 3] = make_int2(st3, st3 + v.w);
}

__global__ void scatter_kernel(const float* __restrict__ x, int n) {
    int i = blockIdx.x * blockDim.x + threadIdx.x;
    if (i >= n) return;
    const float* bx = g_bx;
    float px = x[i * 3 + 0], py = x[i * 3 + 1], pz = x[i * 3 + 2];
    int cx = cell_of(px, bx), cy = cell_of(py, bx), cz = cell_of(pz, bx);
    int cell = (cz * G + cy) * G + cx;
    int slot = atomicAdd(&g_cursor[cell], 1);
    g_pts[slot] = make_float4(px, py, pz, __int_as_float(i));
}

// ============================================================
// kNN query: 2 threads per query. Pair splits candidate cells
// by alternation counter; each keeps an unsorted top-12;
// pair-min dmax shared per ring (pair-masked shfl); snapshot
// merge at the end (race-free).
// ============================================================
__global__ __launch_bounds__(256) void knn_query_kernel(int n) {
    __shared__ float bx[G + 1];
    if (threadIdx.x <= G) bx[threadIdx.x] = g_bx[threadIdx.x];
    __syncthreads();

    int gt = blockIdx.x * blockDim.x + threadIdx.x;
    int s  = gt >> 1;                 // query slot in sorted order
    int a  = gt & 1;                  // pair half
    unsigned pmask = 3u << (threadIdx.x & 30);   // this pair's lanes only
    if (s >= n) return;
    float4 me = g_pts[s];
    float qx = me.x, qy = me.y, qz = me.z;
    int   qi = __float_as_int(me.w);
    int cx = cell_of(qx, bx), cy = cell_of(qy, bx), cz = cell_of(qz, bx);

    float bd[KNN];
    int   bj[KNN];                    // sorted-array slots
#pragma unroll
    for (int r = 0; r < KNN; r++) { bd[r] = 1e30f; bj[r] = 0; }
    float dmax   = 1e30f;             // own 12th best
    int   imax   = 0;
    float dprune = 1e30f;             // min over pair, refreshed per ring
    int   cc     = 0;                 // cell alternation counter

    for (int r = 0; r < G; r++) {
        int zlo = max(cz - r, 0), zhi = min(cz + r, G - 1);
        for (int ccz = zlo; ccz <= zhi; ccz++) {
            bool zface = (ccz == cz - r) || (ccz == cz + r);
            float az = fmaxf(fmaxf(bx[ccz] - qz, qz - bx[ccz + 1]), 0.0f);
            int ylo = max(cy - r, 0), yhi = min(cy + r, G - 1);
            for (int ccy = ylo; ccy <= yhi; ccy++) {
                bool face = zface || (ccy == cy - r) || (ccy == cy + r);
                float ay = fmaxf(fmaxf(bx[ccy] - qy, qy - bx[ccy + 1]), 0.0f);
                float ayz = fmaf(ay, ay, az * az);
                int step = face ? 1 : (2 * r);
                for (int dx = -r; dx <= r; dx += step) {
                    int ccx = cx + dx;
                    if (ccx < 0 || ccx >= G) continue;
                    int take = (cc++) & 1;        // deterministic split
                    if (take != a) continue;
                    float dp = fminf(dprune, dmax);
                    if (ayz >= dp) continue;
                    float ax = fmaxf(fmaxf(bx[ccx] - qx, qx - bx[ccx + 1]), 0.0f);
                    float dmin = fmaf(ax, ax, ayz);
                    if (dmin >= dp) continue;
                    int2 se = g_cell2[(ccz * G + ccy) * G + ccx];
                    for (int j = se.x; j < se.y; j++) {
                        float4 p = g_pts[j];
                        float ddx = p.x - qx, ddy = p.y - qy, ddz = p.z - qz;
                        float d = fmaf(ddx, ddx, fmaf(ddy, ddy, ddz * ddz));
                        if (d < dmax && j != s) {
                            bd[imax] = d;
                            bj[imax] = j;
                            dmax = bd[0]; imax = 0;
#pragma unroll
                            for (int t = 1; t < KNN; t++)
                                if (bd[t] > dmax) { dmax = bd[t]; imax = t; }
                        }
                    }
                }
            }
        }
        // share pair bound (pair-masked shfl); exact stop rule
        float pdm = __shfl_xor_sync(pmask, dmax, 1);
        dprune = fminf(dmax, pdm);
        float f = 1e30f;
        if (cx - r > 0)      f = fminf(f, qx - bx[cx - r]);
        if (cx + r + 1 < G)  f = fminf(f, bx[cx + r + 1] - qx);
        if (cy - r > 0)      f = fminf(f, qy - bx[cy - r]);
        if (cy + r + 1 < G)  f = fminf(f, bx[cy + r + 1] - qy);
        if (cz - r > 0)      f = fminf(f, qz - bx[cz - r]);
        if (cz + r + 1 < G)  f = fminf(f, bx[cz + r + 1] - qz);
        if (f * f >= dprune) break;   // same decision for both pair threads
    }

    // snapshot partner's top-12 FIRST (race-free), then merge
    float pd[KNN]; int pj[KNN];
#pragma unroll
    for (int t = 0; t < KNN; t++) {
        pd[t] = __shfl_xor_sync(pmask, bd[t], 1);
        pj[t] = __shfl_xor_sync(pmask, bj[t], 1);
    }
    if (a) return;                    // only pair-lead merges & writes
#pragma unroll
    for (int t = 0; t < KNN; t++) {
        if (pd[t] < dmax) {
            bd[imax] = pd[t];
            bj[imax] = pj[t];
            dmax = bd[0]; imax = 0;
#pragma unroll
            for (int u = 1; u < KNN; u++)
                if (bd[u] > dmax) { dmax = bd[u]; imax = u; }
        }
    }

    // emit indices + rel_feat (single pass: mean & E[r^2]-m^2 std)
    float sx = 0, sy = 0, sz = 0, sxx = 0, syy = 0, szz = 0;
#pragma unroll
    for (int r = 0; r < KNN; r++) {
        float4 p = g_pts[bj[r]];
        g_knn[qi * KNN + r] = __float_as_int(p.w);
        float rx = p.x - qx, ry = p.y - qy, rz = p.z - qz;
        sx += rx; sy += ry; sz += rz;
        sxx = fmaf(rx, rx, sxx); syy = fmaf(ry, ry, syy); szz = fmaf(rz, rz, szz);
    }
    const float inv = 1.0f / (float)KNN;
    float mx = sx * inv, my = sy * inv, mz = sz * inv;
    g_rel[qi * 6 + 0] = mx;
    g_rel[qi * 6 + 1] = my;
    g_rel[qi * 6 + 2] = mz;
    g_rel[qi * 6 + 3] = sqrtf(fmaxf(sxx * inv - mx * mx, 0.0f));
    g_rel[qi * 6 + 4] = sqrtf(fmaxf(syy * inv - my * my, 0.0f));
    g_rel[qi * 6 + 5] = sqrtf(fmaxf(szz * inv - mz * mz, 0.0f));
}

// ============================================================
// Projection: pe = fourier(x) (51 dims), h0 = silu(pe@Wp[0:51] + zwpb)
// ============================================================
__global__ __launch_bounds__(192) void proj_kernel(const float* __restrict__ x,
                                                   const float* __restrict__ B0,
                                                   const float* __restrict__ B1,
                                                   const float* __restrict__ B2,
                                                   const float* __restrict__ Wp,
                                                   float* __restrict__ hout) {
    __shared__ float pe[TPL][52];
    int c    = threadIdx.x;
    int base = blockIdx.x * TPL;

    if (c < TPL) {
        int p = base + c;
        float x0 = x[p * 3 + 0], x1 = x[p * 3 + 1], x2 = x[p * 3 + 2];
        const float* Bs[3] = { B0, B1, B2 };
#pragma unroll
        for (int b = 0; b < 3; b++) {
            const float* B = Bs[b];
#pragma unroll
            for (int j = 0; j < 8; j++) {
                float v = fmaf(x0, B[j], fmaf(x1, B[8 + j], x2 * B[16 + j]));
                float sn, cs;
                sincosf(v, &sn, &cs);
                pe[c][b * 16 + j]     = sn;
                pe[c][b * 16 + 8 + j] = cs;
            }
        }
        pe[c][48] = x0; pe[c][49] = x1; pe[c][50] = x2;
    }
    __syncthreads();

    float acc[TPL];
    float zb = g_zwpb[c];
#pragma unroll
    for (int p = 0; p < TPL; p++) acc[p] = zb;
    for (int k = 0; k < 51; k++) {
        float w = Wp[k * WIDTH + c];
#pragma unroll
        for (int p = 0; p < TPL; p++)
            acc[p] = fmaf(pe[p][k], w, acc[p]);
    }
#pragma unroll
    for (int p = 0; p < TPL; p++) {
        float v = acc[p];
        hout[(base + p) * WIDTH + c] = v / (1.0f + expf(-v));
    }
}

// ============================================================
// Layer: gather+mean agg, mix=[h|agg|rel], 390x192 GEMM with
// packed f32x2 FMA, silu + FiLM. 16 points/block, 192 threads.
// ============================================================
__global__ __launch_bounds__(192) void layer_kernel(const float* __restrict__ hin,
                                                    float* __restrict__ hout,
                                                    const float* __restrict__ Wl,
                                                    const float* __restrict__ bl,
                                                    const float* __restrict__ gamma,
                                                    const float* __restrict__ beta) {
    __shared__ float mix[TPL2 * MIXPAD];     // 25088 B
    __shared__ int   nidx[TPL2 * KNN];       // 192
    int c    = threadIdx.x;
    int base = blockIdx.x * TPL2;

    nidx[c] = g_knn[base * KNN + c];         // exactly 192 = 16*12
    __syncthreads();

#pragma unroll
    for (int p = 0; p < TPL2; p++)
        mix[p * MIXPAD + c] = hin[(base + p) * WIDTH + c];
    if (c < 6) {
#pragma unroll
        for (int p = 0; p < TPL2; p++)
            mix[p * MIXPAD + 384 + c] = g_rel[(base + p) * 6 + c];
    }
#pragma unroll 2
    for (int p = 0; p < TPL2; p++) {
        float s = 0.0f;
#pragma unroll
        for (int j = 0; j < KNN; j++)
            s += hin[nidx[p * KNN + j] * WIDTH + c];
        mix[p * MIXPAD + WIDTH + c] = s * (1.0f / (float)KNN);
    }
    __syncthreads();

    ull acc[TPL2];
#pragma unroll
    for (int p = 0; p < TPL2; p++) acc[p] = 0ull;

    for (int k4 = 0; k4 < 97; k4++) {
        int k = k4 * 4;
        float w0 = Wl[(k + 0) * WIDTH + c];
        float w1 = Wl[(k + 1) * WIDTH + c];
        float w2 = Wl[(k + 2) * WIDTH + c];
        float w3 = Wl[(k + 3) * WIDTH + c];
        ull w01 = pk2(w0, w1), w23 = pk2(w2, w3);
#pragma unroll
        for (int p = 0; p < TPL2; p++) {
            ulonglong2 m = *reinterpret_cast<const ulonglong2*>(&mix[p * MIXPAD + k]);
            acc[p] = fma2(m.x, w01, acc[p]);
            acc[p] = fma2(m.y, w23, acc[p]);
        }
    }
    {   // tail k = 388, 389
        ull w01 = pk2(Wl[388 * WIDTH + c], Wl[389 * WIDTH + c]);
#pragma unroll
        for (int p = 0; p < TPL2; p++) {
            ull m = *reinterpret_cast<const ull*>(&mix[p * MIXPAD + 388]);
            acc[p] = fma2(m, w01, acc[p]);
        }
    }

    float bc = bl[c], gc = gamma[c], bt = beta[c];
#pragma unroll
    for (int p = 0; p < TPL2; p++) {
        float aa, bb2;
        upk2(acc[p], aa, bb2);
        float v  = aa + bb2 + bc;
        float sv = v / (1.0f + expf(-v));
        hout[(base + p) * WIDTH + c] = fmaf(sv, gc, bt);
    }
}

// ============================================================
// Output: out = (h @ Wout + bout) * 0.01 ; one warp per point
// ============================================================
__global__ __launch_bounds__(256) void out_kernel(const float* __restrict__ h,
                                                  const float* __restrict__ Wout,
                                                  const float* __restrict__ bout,
                                                  float* __restrict__ out, int n) {
    int gwarp = (blockIdx.x * blockDim.x + threadIdx.x) >> 5;
    int lane  = threadIdx.x & 31;
    if (gwarp >= n) return;
    float o0 = 0, o1 = 0, o2 = 0;
    for (int c = lane; c < WIDTH; c += 32) {
        float hv = h[gwarp * WIDTH + c];
        o0 = fmaf(hv, Wout[c * 3 + 0], o0);
        o1 = fmaf(hv, Wout[c * 3 + 1], o1);
        o2 = fmaf(hv, Wout[c * 3 + 2], o2);
    }
#pragma unroll
    for (int off = 16; off; off >>= 1) {
        o0 += __shfl_down_sync(0xffffffffu, o0, off);
        o1 += __shfl_down_sync(0xffffffffu, o1, off);
        o2 += __shfl_down_sync(0xffffffffu, o2, off);
    }
    if (lane == 0) {
        out[gwarp * 3 + 0] = (o0 + bout[0]) * 0.01f;
        out[gwarp * 3 + 1] = (o1 + bout[1]) * 0.01f;
        out[gwarp * 3 + 2] = (o2 + bout[2]) * 0.01f;
    }
}

// ============================================================
extern "C" void kernel_launch(void* const* d_in, const int* in_sizes, int n_in,
                              void* d_out, int out_size) {
    const float* x    = (const float*)d_in[0];
    const float* z    = (const float*)d_in[1];
    const float* B0   = (const float*)d_in[2];
    const float* B1   = (const float*)d_in[3];
    const float* B2   = (const float*)d_in[4];
    const float* Wp   = (const float*)d_in[5];
    const float* bp   = (const float*)d_in[6];
    const float* Wl   = (const float*)d_in[7];
    const float* bl   = (const float*)d_in[8];
    const float* Wg   = (const float*)d_in[9];
    const float* bg   = (const float*)d_in[10];
    const float* Wb   = (const float*)d_in[11];
    const float* Wbb  = (const float*)d_in[12];
    const float* Wout = (const float*)d_in[13];
    const float* bout = (const float*)d_in[14];
    float* out = (float*)d_out;

    int n = in_sizes[0] / 3;   // 32768

    float *h0, *h1;
    cudaGetSymbolAddress((void**)&h0, g_h0);
    cudaGetSymbolAddress((void**)&h1, g_h1);
    float *gma, *bta;
    cudaGetSymbolAddress((void**)&gma, g_gamma);
    cudaGetSymbolAddress((void**)&bta, g_beta);
    void* cntp;
    cudaGetSymbolAddress(&cntp, g_cnt);

    cudaMemsetAsync(cntp, 0, NCELLS * sizeof(int));
    setup_kernel<<<1, WIDTH>>>(z, Wp, bp, Wg, bg, Wb, Wbb);      // 0
    hist_kernel<<<n / 256, 256>>>(x, n);                         // 1
    scan_kernel<<<1, 1024>>>();                                  // 2
    scatter_kernel<<<n / 256, 256>>>(x, n);                      // 3 (profiled slot)
    knn_query_kernel<<<(n * 2) / 256, 256>>>(n);                 // 4
    proj_kernel<<<n / TPL, WIDTH>>>(x, B0, B1, B2, Wp, h0);      // 5

    float* bufs[2] = { h0, h1 };
    for (int li = 0; li < NLAYERS; li++) {
        const float* hin = bufs[li & 1];
        float*       ho  = bufs[(li + 1) & 1];
        layer_kernel<<<n / TPL2, 192>>>(hin, ho,
            Wl + (size_t)li * MIXDIM * WIDTH, bl + li * WIDTH,
            gma + li * WIDTH, bta + li * WIDTH);
    }
    const float* hfin = bufs[NLAYERS & 1];

    out_kernel<<<(n * 32 + 255) / 256, 256>>>(hfin, Wout, bout, out, n);
}

// round 7
// speedup vs baseline: 1.3924x; 1.1421x over previous
#include <cuda_runtime.h>
#include <math.h>

#define NPTS    32768
#define WIDTH   192
#define COND    64
#define KNN     12
#define NLAYERS 4
#define MIXDIM  390
#define MIXPAD  392
#define TPL     32      // points per block (proj)
#define TPLL    32      // points per block (layer)

// ---- quantile grid for kNN ----
#define G       16
#define NCELLS  (G*G*G)          // 4096

typedef unsigned long long ull;

// ---- scratch (static device allocations; no cudaMalloc allowed) ----
__device__ float  g_h0[NPTS * WIDTH];
__device__ float  g_h1[NPTS * WIDTH];
__device__ int    g_knn[NPTS * KNN];
__device__ float  g_rel[NPTS * 6];
__device__ float  g_zwpb[WIDTH];
__device__ float  g_gamma[NLAYERS * WIDTH];
__device__ float  g_beta[NLAYERS * WIDTH];

__device__ float  g_bx[G + 1];        // quantile boundaries in x-space
__device__ int    g_cnt[NCELLS];
__device__ int    g_cursor[NCELLS];
__device__ int2   g_cell2[NCELLS];    // (start, end)
__device__ float4 g_pts[NPTS];        // sorted (x,y,z, orig-idx-as-bits)

// ---- packed f32x2 helpers (FFMA2) ----
__device__ __forceinline__ ull pk2(float a, float b) {
    ull r; asm("mov.b64 %0,{%1,%2};" : "=l"(r) : "f"(a), "f"(b)); return r;
}
__device__ __forceinline__ ull fma2(ull a, ull b, ull c) {
    ull d; asm("fma.rn.f32x2 %0,%1,%2,%3;" : "=l"(d) : "l"(a), "l"(b), "l"(c)); return d;
}
__device__ __forceinline__ void upk2(ull v, float& a, float& b) {
    asm("mov.b64 {%0,%1},%2;" : "=f"(a), "=f"(b) : "l"(v));
}

__device__ __forceinline__ int cell_of(float v, const float* bx) {
    int lo = 0;
    if (v >= bx[8])      lo = 8;
    if (v >= bx[lo + 4]) lo += 4;
    if (v >= bx[lo + 2]) lo += 2;
    if (v >= bx[lo + 1]) lo += 1;
    return lo;           // bx[lo] <= v < bx[lo+1]
}

// ============================================================
// Setup: zero grid counters + z-dependent constants + quantiles
// ============================================================
__global__ void setup_kernel(const float* __restrict__ z,
                             const float* __restrict__ Wp, const float* __restrict__ bp,
                             const float* __restrict__ Wg, const float* __restrict__ bg,
                             const float* __restrict__ Wb, const float* __restrict__ bb) {
    int c = threadIdx.x;
    for (int i = c; i < NCELLS; i += blockDim.x) g_cnt[i] = 0;
    if (c <= G) {
        g_bx[c] = (c == 0) ? -1e9f : ((c == G) ? 1e9f
                  : normcdfinvf((float)c / (float)G));
    }
    if (c >= WIDTH) return;
    float s = bp[c];
    for (int k = 0; k < COND; k++)
        s = fmaf(z[k], Wp[(51 + k) * WIDTH + c], s);
    g_zwpb[c] = s;
    for (int li = 0; li < NLAYERS; li++) {
        const float* wg = Wg + li * COND * WIDTH;
        const float* wb = Wb + li * COND * WIDTH;
        float g = bg[li * WIDTH + c];
        float b = bb[li * WIDTH + c];
        for (int k = 0; k < COND; k++) {
            float zk = z[k];
            g = fmaf(zk, wg[k * WIDTH + c], g);
            b = fmaf(zk, wb[k * WIDTH + c], b);
        }
        g_gamma[li * WIDTH + c] = g;
        g_beta[li * WIDTH + c]  = b;
    }
}

// ============================================================
// Grid build: histogram -> single-block scan -> scatter
// ============================================================
__global__ void hist_kernel(const float* __restrict__ x, int n) {
    int i = blockIdx.x * blockDim.x + threadIdx.x;
    if (i >= n) return;
    const float* bx = g_bx;
    int cx = cell_of(x[i * 3 + 0], bx);
    int cy = cell_of(x[i * 3 + 1], bx);
    int cz = cell_of(x[i * 3 + 2], bx);
    atomicAdd(&g_cnt[(cz * G + cy) * G + cx], 1);
}

__global__ void scan_kernel() {   // 1024 threads, 4 cells each
    __shared__ int sh[1024];
    int t = threadIdx.x;
    int4 v = *reinterpret_cast<const int4*>(&g_cnt[t * 4]);
    int s = v.x + v.y + v.z + v.w;
    sh[t] = s;
    __syncthreads();
    for (int off = 1; off < 1024; off <<= 1) {
        int u = (t >= off) ? sh[t - off] : 0;
        __syncthreads();
        sh[t] += u;
        __syncthreads();
    }
    int ex = sh[t] - s;
    int st0 = ex, st1 = st0 + v.x, st2 = st1 + v.y, st3 = st2 + v.z;
    g_cursor[t * 4 + 0] = st0;  g_cell2[t * 4 + 0] = make_int2(st0, st1);
    g_cursor[t * 4 + 1] = st1;  g_cell2[t * 4 + 1] = make_int2(st1, st2);
    g_cursor[t * 4 + 2] = st2;  g_cell2[t * 4 + 2] = make_int2(st2, st3);
    g_cursor[t * 4 + 3] = st3;  g_cell2[t * 4 + 3] = make_int2(st3, st3 + v.w);
}

__global__ void scatter_kernel(const float* __restrict__ x, int n) {
    int i = blockIdx.x * blockDim.x + threadIdx.x;
    if (i >= n) return;
    const float* bx = g_bx;
    float px = x[i * 3 + 0], py = x[i * 3 + 1], pz = x[i * 3 + 2];
    int cx = cell_of(px, bx), cy = cell_of(py, bx), cz = cell_of(pz, bx);
    int cell = (cz * G + cy) * G + cx;
    int slot = atomicAdd(&g_cursor[cell], 1);
    g_pts[slot] = make_float4(px, py, pz, __int_as_float(i));
}

// ============================================================
// kNN query: one thread per sorted point; expanding Chebyshev
// rings, AABB pruning, exact stop; unsorted top-12 w/ max-slot.
// (R4 version, measured 293us; 128-thread blocks.)
// ============================================================
__global__ __launch_bounds__(128) void knn_query_kernel(int n) {
    __shared__ float bx[G + 1];
    if (threadIdx.x <= G) bx[threadIdx.x] = g_bx[threadIdx.x];
    __syncthreads();

    int s = blockIdx.x * blockDim.x + threadIdx.x;
    if (s >= n) return;
    float4 me = g_pts[s];
    float qx = me.x, qy = me.y, qz = me.z;
    int   qi = __float_as_int(me.w);
    int cx = cell_of(qx, bx), cy = cell_of(qy, bx), cz = cell_of(qz, bx);

    float bd[KNN];
    int   bj[KNN];                    // sorted-array slots
#pragma unroll
    for (int r = 0; r < KNN; r++) { bd[r] = 1e30f; bj[r] = 0; }
    float dmax = 1e30f;
    int   imax = 0;

    for (int r = 0; r < G; r++) {
        int zlo = max(cz - r, 0), zhi = min(cz + r, G - 1);
        for (int ccz = zlo; ccz <= zhi; ccz++) {
            bool zface = (ccz == cz - r) || (ccz == cz + r);
            float az = fmaxf(fmaxf(bx[ccz] - qz, qz - bx[ccz + 1]), 0.0f);
            int ylo = max(cy - r, 0), yhi = min(cy + r, G - 1);
            for (int ccy = ylo; ccy <= yhi; ccy++) {
                bool face = zface || (ccy == cy - r) || (ccy == cy + r);
                float ay = fmaxf(fmaxf(bx[ccy] - qy, qy - bx[ccy + 1]), 0.0f);
                float ayz = fmaf(ay, ay, az * az);
                if (ayz >= dmax) continue;
                int step = face ? 1 : (2 * r);
                for (int dx = -r; dx <= r; dx += step) {
                    int ccx = cx + dx;
                    if (ccx < 0 || ccx >= G) continue;
                    float ax = fmaxf(fmaxf(bx[ccx] - qx, qx - bx[ccx + 1]), 0.0f);
                    float dmin = fmaf(ax, ax, ayz);
                    if (dmin >= dmax) continue;
                    int2 se = g_cell2[(ccz * G + ccy) * G + ccx];
                    for (int j = se.x; j < se.y; j++) {
                        float4 p = g_pts[j];
                        float ddx = p.x - qx, ddy = p.y - qy, ddz = p.z - qz;
                        float d = fmaf(ddx, ddx, fmaf(ddy, ddy, ddz * ddz));
                        if (d < dmax && j != s) {
                            bd[imax] = d;
                            bj[imax] = j;
                            dmax = bd[0]; imax = 0;
#pragma unroll
                            for (int t = 1; t < KNN; t++)
                                if (bd[t] > dmax) { dmax = bd[t]; imax = t; }
                        }
                    }
                }
            }
        }
        // exact stop: min distance from q to complement of searched box
        float f = 1e30f;
        if (cx - r > 0)      f = fminf(f, qx - bx[cx - r]);
        if (cx + r + 1 < G)  f = fminf(f, bx[cx + r + 1] - qx);
        if (cy - r > 0)      f = fminf(f, qy - bx[cy - r]);
        if (cy + r + 1 < G)  f = fminf(f, bx[cy + r + 1] - qy);
        if (cz - r > 0)      f = fminf(f, qz - bx[cz - r]);
        if (cz + r + 1 < G)  f = fminf(f, bx[cz + r + 1] - qz);
        if (f * f >= dmax) break;
    }

    // emit indices + rel_feat (single pass: mean & E[r^2]-m^2 std)
    float sx = 0, sy = 0, sz = 0, sxx = 0, syy = 0, szz = 0;
#pragma unroll
    for (int r = 0; r < KNN; r++) {
        float4 p = g_pts[bj[r]];
        g_knn[qi * KNN + r] = __float_as_int(p.w);
        float rx = p.x - qx, ry = p.y - qy, rz = p.z - qz;
        sx += rx; sy += ry; sz += rz;
        sxx = fmaf(rx, rx, sxx); syy = fmaf(ry, ry, syy); szz = fmaf(rz, rz, szz);
    }
    const float inv = 1.0f / (float)KNN;
    float mx = sx * inv, my = sy * inv, mz = sz * inv;
    g_rel[qi * 6 + 0] = mx;
    g_rel[qi * 6 + 1] = my;
    g_rel[qi * 6 + 2] = mz;
    g_rel[qi * 6 + 3] = sqrtf(fmaxf(sxx * inv - mx * mx, 0.0f));
    g_rel[qi * 6 + 4] = sqrtf(fmaxf(syy * inv - my * my, 0.0f));
    g_rel[qi * 6 + 5] = sqrtf(fmaxf(szz * inv - mz * mz, 0.0f));
}

// ============================================================
// Projection: pe = fourier(x) (51 dims), h0 = silu(pe@Wp[0:51] + zwpb)
// ============================================================
__global__ __launch_bounds__(192) void proj_kernel(const float* __restrict__ x,
                                                   const float* __restrict__ B0,
                                                   const float* __restrict__ B1,
                                                   const float* __restrict__ B2,
                                                   const float* __restrict__ Wp,
                                                   float* __restrict__ hout) {
    __shared__ float pe[TPL][52];
    int c    = threadIdx.x;
    int base = blockIdx.x * TPL;

    if (c < TPL) {
        int p = base + c;
        float x0 = x[p * 3 + 0], x1 = x[p * 3 + 1], x2 = x[p * 3 + 2];
        const float* Bs[3] = { B0, B1, B2 };
#pragma unroll
        for (int b = 0; b < 3; b++) {
            const float* B = Bs[b];
#pragma unroll
            for (int j = 0; j < 8; j++) {
                float v = fmaf(x0, B[j], fmaf(x1, B[8 + j], x2 * B[16 + j]));
                float sn, cs;
                sincosf(v, &sn, &cs);
                pe[c][b * 16 + j]     = sn;
                pe[c][b * 16 + 8 + j] = cs;
            }
        }
        pe[c][48] = x0; pe[c][49] = x1; pe[c][50] = x2;
    }
    __syncthreads();

    float acc[TPL];
    float zb = g_zwpb[c];
#pragma unroll
    for (int p = 0; p < TPL; p++) acc[p] = zb;
    for (int k = 0; k < 51; k++) {
        float w = Wp[k * WIDTH + c];
#pragma unroll
        for (int p = 0; p < TPL; p++)
            acc[p] = fmaf(pe[p][k], w, acc[p]);
    }
#pragma unroll
    for (int p = 0; p < TPL; p++) {
        float v = acc[p];
        hout[(base + p) * WIDTH + c] = v / (1.0f + expf(-v));
    }
}

// ============================================================
// Layer: gather+mean agg, mix=[h|agg|rel], 390x192 GEMM.
// 192 threads = 2 subgroups of 96; each thread owns 2 output
// columns (c, c+96) x 16 points -> each broadcast LDS.128 of a
// mix-quad feeds 4 FFMA2 (2x register reuse vs 1-col version).
// ============================================================
__global__ __launch_bounds__(192) void layer_kernel(const float* __restrict__ hin,
                                                    float* __restrict__ hout,
                                                    const float* __restrict__ Wl,
                                                    const float* __restrict__ bl,
                                                    const float* __restrict__ gamma,
                                                    const float* __restrict__ beta) {
    extern __shared__ float mix[];           // [TPLL][MIXPAD] = 50176 B
    __shared__ int nidx[TPLL * KNN];         // 384
    int tid  = threadIdx.x;
    int base = blockIdx.x * TPLL;
    int sub  = tid / 96;                     // point subgroup 0/1
    int c0   = tid - sub * 96;               // 0..95
    int c1   = c0 + 96;

    nidx[tid]       = g_knn[base * KNN + tid];
    nidx[tid + 192] = g_knn[base * KNN + tid + 192];
    __syncthreads();

#pragma unroll 4
    for (int p = 0; p < TPLL; p++)
        mix[p * MIXPAD + tid] = hin[(base + p) * WIDTH + tid];
    if (tid < 6) {
#pragma unroll 4
        for (int p = 0; p < TPLL; p++)
            mix[p * MIXPAD + 384 + tid] = g_rel[(base + p) * 6 + tid];
    }
#pragma unroll 2
    for (int p = 0; p < TPLL; p++) {
        float s = 0.0f;
#pragma unroll
        for (int j = 0; j < KNN; j++)
            s += hin[nidx[p * KNN + j] * WIDTH + tid];
        mix[p * MIXPAD + WIDTH + tid] = s * (1.0f / (float)KNN);
    }
    __syncthreads();

    ull a0[16], a1[16];
#pragma unroll
    for (int p = 0; p < 16; p++) { a0[p] = 0ull; a1[p] = 0ull; }
    const float* mrow = mix + sub * 16 * MIXPAD;

    for (int k4 = 0; k4 < 97; k4++) {
        int k = k4 * 4;
        const float* wr = Wl + k * WIDTH;
        ull wa01 = pk2(wr[c0],             wr[WIDTH + c0]);
        ull wa23 = pk2(wr[2 * WIDTH + c0], wr[3 * WIDTH + c0]);
        ull wb01 = pk2(wr[c1],             wr[WIDTH + c1]);
        ull wb23 = pk2(wr[2 * WIDTH + c1], wr[3 * WIDTH + c1]);
#pragma unroll
        for (int p = 0; p < 16; p++) {
            ulonglong2 m = *reinterpret_cast<const ulonglong2*>(&mrow[p * MIXPAD + k]);
            a0[p] = fma2(m.x, wa01, a0[p]);
            a0[p] = fma2(m.y, wa23, a0[p]);
            a1[p] = fma2(m.x, wb01, a1[p]);
            a1[p] = fma2(m.y, wb23, a1[p]);
        }
    }
    {   // tail k = 388, 389
        ull wta = pk2(Wl[388 * WIDTH + c0], Wl[389 * WIDTH + c0]);
        ull wtb = pk2(Wl[388 * WIDTH + c1], Wl[389 * WIDTH + c1]);
#pragma unroll
        for (int p = 0; p < 16; p++) {
            ull m = *reinterpret_cast<const ull*>(&mrow[p * MIXPAD + 388]);
            a0[p] = fma2(m, wta, a0[p]);
            a1[p] = fma2(m, wtb, a1[p]);
        }
    }

    float bc0 = bl[c0], g0 = gamma[c0], t0 = beta[c0];
    float bc1 = bl[c1], g1 = gamma[c1], t1 = beta[c1];
#pragma unroll
    for (int p = 0; p < 16; p++) {
        int pp = base + sub * 16 + p;
        float xa, xb;
        upk2(a0[p], xa, xb);
        float v0  = xa + xb + bc0;
        float sv0 = v0 / (1.0f + expf(-v0));
        hout[pp * WIDTH + c0] = fmaf(sv0, g0, t0);
        upk2(a1[p], xa, xb);
        float v1  = xa + xb + bc1;
        float sv1 = v1 / (1.0f + expf(-v1));
        hout[pp * WIDTH + c1] = fmaf(sv1, g1, t1);
    }
}

// ============================================================
// Output: out = (h @ Wout + bout) * 0.01 ; one warp per point
// ============================================================
__global__ __launch_bounds__(256) void out_kernel(const float* __restrict__ h,
                                                  const float* __restrict__ Wout,
                                                  const float* __restrict__ bout,
                                                  float* __restrict__ out, int n) {
    int gwarp = (blockIdx.x * blockDim.x + threadIdx.x) >> 5;
    int lane  = threadIdx.x & 31;
    if (gwarp >= n) return;
    float o0 = 0, o1 = 0, o2 = 0;
    for (int c = lane; c < WIDTH; c += 32) {
        float hv = h[gwarp * WIDTH + c];
        o0 = fmaf(hv, Wout[c * 3 + 0], o0);
        o1 = fmaf(hv, Wout[c * 3 + 1], o1);
        o2 = fmaf(hv, Wout[c * 3 + 2], o2);
    }
#pragma unroll
    for (int off = 16; off; off >>= 1) {
        o0 += __shfl_down_sync(0xffffffffu, o0, off);
        o1 += __shfl_down_sync(0xffffffffu, o1, off);
        o2 += __shfl_down_sync(0xffffffffu, o2, off);
    }
    if (lane == 0) {
        out[gwarp * 3 + 0] = (o0 + bout[0]) * 0.01f;
        out[gwarp * 3 + 1] = (o1 + bout[1]) * 0.01f;
        out[gwarp * 3 + 2] = (o2 + bout[2]) * 0.01f;
    }
}

// ============================================================
extern "C" void kernel_launch(void* const* d_in, const int* in_sizes, int n_in,
                              void* d_out, int out_size) {
    const float* x    = (const float*)d_in[0];
    const float* z    = (const float*)d_in[1];
    const float* B0   = (const float*)d_in[2];
    const float* B1   = (const float*)d_in[3];
    const float* B2   = (const float*)d_in[4];
    const float* Wp   = (const float*)d_in[5];
    const float* bp   = (const float*)d_in[6];
    const float* Wl   = (const float*)d_in[7];
    const float* bl   = (const float*)d_in[8];
    const float* Wg   = (const float*)d_in[9];
    const float* bg   = (const float*)d_in[10];
    const float* Wb   = (const float*)d_in[11];
    const float* Wbb  = (const float*)d_in[12];
    const float* Wout = (const float*)d_in[13];
    const float* bout = (const float*)d_in[14];
    float* out = (float*)d_out;

    int n = in_sizes[0] / 3;   // 32768

    float *h0, *h1;
    cudaGetSymbolAddress((void**)&h0, g_h0);
    cudaGetSymbolAddress((void**)&h1, g_h1);
    float *gma, *bta;
    cudaGetSymbolAddress((void**)&gma, g_gamma);
    cudaGetSymbolAddress((void**)&bta, g_beta);

    const int smem_layer = TPLL * MIXPAD * (int)sizeof(float);  // 50176
    cudaFuncSetAttribute(layer_kernel, cudaFuncAttributeMaxDynamicSharedMemorySize, smem_layer);

    setup_kernel<<<1, WIDTH>>>(z, Wp, bp, Wg, bg, Wb, Wbb);      // 0 (also zeroes g_cnt)
    hist_kernel<<<n / 256, 256>>>(x, n);                         // 1
    scan_kernel<<<1, 1024>>>();                                  // 2
    scatter_kernel<<<n / 256, 256>>>(x, n);                      // 3
    knn_query_kernel<<<n / 128, 128>>>(n);                       // 4 (profiled slot)
    proj_kernel<<<n / TPL, WIDTH>>>(x, B0, B1, B2, Wp, h0);      // 5

    float* bufs[2] = { h0, h1 };
    for (int li = 0; li < NLAYERS; li++) {
        const float* hin = bufs[li & 1];
        float*       ho  = bufs[(li + 1) & 1];
        layer_kernel<<<n / TPLL, 192, smem_layer>>>(hin, ho,
            Wl + (size_t)li * MIXDIM * WIDTH, bl + li * WIDTH,
            gma + li * WIDTH, bta + li * WIDTH);
    }
    const float* hfin = bufs[NLAYERS & 1];

    out_kernel<<<(n * 32 + 255) / 256, 256>>>(hfin, Wout, bout, out, n);
}